// round 1
// baseline (speedup 1.0000x reference)
#include <cuda_runtime.h>

// GCN: out = log_softmax( agg( relu( agg(x@W1) + b1 ) @ W2 ) + b2 )
// agg uses symmetric D^-1/2 (A+I) D^-1/2 with in-degree (dst) + self loops.

#define NN 100000
#define EE 1600000
#define FF 256
#define HH 64
#define CC 16
#define NB1 98           // ceil(NN/1024)

// ---------------- scratch (static device globals; no allocation) -------------
__device__ int   g_deg[NN];
__device__ int   g_start[NN + 1];
__device__ int   g_cursor[NN];
__device__ float g_dinv[NN];
__device__ int2  g_csr[EE];              // .x = src node, .y = float bits of norm weight
__device__ float g_h1[(size_t)NN * HH];  // x @ W1
__device__ float g_x2[(size_t)NN * HH];  // relu(agg1 + b1)
__device__ float g_z [(size_t)NN * CC];  // x2 @ W2
__device__ int   g_bsum[128];
__device__ int   g_is64;                 // edge_index stored as int64 (vs int32)

// ---------------- dtype detection for edge_index ----------------------------
__global__ void k_detect(const int* __restrict__ ei32) {
    if (threadIdx.x == 0 && blockIdx.x == 0) {
        int s = 0;
        // if int64 little-endian, every odd 32-bit word is 0 (values < 2^17)
        for (int i = 0; i < 64; ++i) s |= ei32[2 * i + 1];
        g_is64 = (s == 0) ? 1 : 0;
    }
}

__device__ __forceinline__ int edge_at(const void* ei, long long idx) {
    if (g_is64) return (int)((const long long*)ei)[idx];
    return ((const int*)ei)[idx];
}

// ---------------- degree / scan / CSR build ---------------------------------
__global__ void k_zero() {
    int i = blockIdx.x * blockDim.x + threadIdx.x;
    if (i < NN) g_deg[i] = 0;
}

__global__ void k_hist(const void* __restrict__ ei) {
    int e = blockIdx.x * blockDim.x + threadIdx.x;
    if (e >= EE) return;
    int d = edge_at(ei, (long long)EE + e);   // dst row
    atomicAdd(&g_deg[d], 1);
}

__global__ void k_dinv() {
    int i = blockIdx.x * blockDim.x + threadIdx.x;
    if (i < NN) g_dinv[i] = rsqrtf((float)(g_deg[i] + 1));   // +1 self loop
}

__global__ void k_scan1() {
    __shared__ int s[1024];
    int t = threadIdx.x;
    int i = blockIdx.x * 1024 + t;
    int v = (i < NN) ? g_deg[i] : 0;
    s[t] = v;
    __syncthreads();
    for (int off = 1; off < 1024; off <<= 1) {
        int add = (t >= off) ? s[t - off] : 0;
        __syncthreads();
        s[t] += add;
        __syncthreads();
    }
    if (i < NN) g_start[i] = s[t] - v;        // exclusive within block
    if (t == 1023) g_bsum[blockIdx.x] = s[t]; // block total
}

__global__ void k_scan2() {
    __shared__ int sb[128];
    int t = threadIdx.x;
    sb[t] = (t < NB1) ? g_bsum[t] : 0;
    __syncthreads();
    if (t == 0) {
        int run = 0;
        for (int b = 0; b < NB1; ++b) { int v = sb[b]; sb[b] = run; run += v; }
        g_start[NN] = EE;
    }
    __syncthreads();
    if (t < NB1) g_bsum[t] = sb[t];
}

__global__ void k_scan3() {
    int i = blockIdx.x * 1024 + threadIdx.x;
    if (i < NN) {
        int v = g_start[i] + g_bsum[blockIdx.x];
        g_start[i]  = v;
        g_cursor[i] = v;
    }
}

__global__ void k_scatter(const void* __restrict__ ei) {
    int e = blockIdx.x * blockDim.x + threadIdx.x;
    if (e >= EE) return;
    int s = edge_at(ei, e);
    int d = edge_at(ei, (long long)EE + e);
    float w = g_dinv[s] * g_dinv[d];
    int pos = atomicAdd(&g_cursor[d], 1);
    g_csr[pos] = make_int2(s, __float_as_int(w));
}

// ---------------- GEMM1: h1 = x @ W1  (100000x256 @ 256x64) -----------------
// 64-row x 64-col tile per block of 256 threads, 4x4 register micro-tile.
__global__ void k_gemm1(const float* __restrict__ x, const float* __restrict__ W1) {
    __shared__ float XsT[64][65];   // XsT[k][r], pad 65 -> conflict-free stores
    __shared__ float Ws[64][64];    // Ws[k][c]
    int t = threadIdx.x;
    int row0 = blockIdx.x * 64;
    int tr4 = (t >> 4) << 2;        // row group
    int tc4 = (t & 15) << 2;        // col group
    float acc[4][4] = {};

    for (int k0 = 0; k0 < FF; k0 += 64) {
        // load X tile (64 rows x 64 k), coalesced global, conflict-free smem stores
#pragma unroll
        for (int it = 0; it < 16; ++it) {
            int fid = t + it * 256;
            int r = fid >> 6;
            int k = fid & 63;
            int gr = row0 + r;
            XsT[k][r] = (gr < NN) ? x[(size_t)gr * FF + k0 + k] : 0.f;
        }
        // load W tile (64 k x 64 c)
#pragma unroll
        for (int it = 0; it < 4; ++it) {
            int fid = t + it * 256;
            int k = fid >> 4;
            int c = (fid & 15) << 2;
            *(float4*)&Ws[k][c] = *(const float4*)&W1[(size_t)(k0 + k) * HH + c];
        }
        __syncthreads();
#pragma unroll
        for (int kk = 0; kk < 64; ++kk) {
            float a0 = XsT[kk][tr4 + 0];
            float a1 = XsT[kk][tr4 + 1];
            float a2 = XsT[kk][tr4 + 2];
            float a3 = XsT[kk][tr4 + 3];
            float4 b = *(const float4*)&Ws[kk][tc4];
            acc[0][0] += a0 * b.x; acc[0][1] += a0 * b.y; acc[0][2] += a0 * b.z; acc[0][3] += a0 * b.w;
            acc[1][0] += a1 * b.x; acc[1][1] += a1 * b.y; acc[1][2] += a1 * b.z; acc[1][3] += a1 * b.w;
            acc[2][0] += a2 * b.x; acc[2][1] += a2 * b.y; acc[2][2] += a2 * b.z; acc[2][3] += a2 * b.w;
            acc[3][0] += a3 * b.x; acc[3][1] += a3 * b.y; acc[3][2] += a3 * b.z; acc[3][3] += a3 * b.w;
        }
        __syncthreads();
    }
#pragma unroll
    for (int i = 0; i < 4; ++i) {
        int gr = row0 + tr4 + i;
        if (gr < NN)
            *(float4*)&g_h1[(size_t)gr * HH + tc4] =
                make_float4(acc[i][0], acc[i][1], acc[i][2], acc[i][3]);
    }
}

// ---------------- agg1: x2 = relu( D^-1/2 (A+I) D^-1/2 h1 + b1 ) ------------
// one warp per node, lane l handles dims [2l, 2l+1] as float2
__global__ void k_agg1(const float* __restrict__ b1) {
    int gw = (blockIdx.x * blockDim.x + threadIdx.x) >> 5;
    if (gw >= NN) return;
    int lane = threadIdx.x & 31;
    int n = gw;
    const float2* h1 = (const float2*)g_h1;

    float di = g_dinv[n];
    float selfw = di * di;
    float2 hv = h1[(size_t)n * 32 + lane];
    float2 acc = make_float2(hv.x * selfw, hv.y * selfw);

    int e0 = g_start[n], e1 = g_start[n + 1];
    for (int e = e0; e < e1; ++e) {
        int2  ce = g_csr[e];                    // broadcast 8B load
        float w  = __int_as_float(ce.y);
        float2 v = h1[(size_t)ce.x * 32 + lane];
        acc.x += w * v.x;
        acc.y += w * v.y;
    }
    float2 bb = ((const float2*)b1)[lane];
    acc.x = fmaxf(acc.x + bb.x, 0.f);
    acc.y = fmaxf(acc.y + bb.y, 0.f);
    ((float2*)g_x2)[(size_t)n * 32 + lane] = acc;
}

// ---------------- GEMM2: z = x2 @ W2  (100000x64 @ 64x16) -------------------
// 64-node tile per block of 256 threads; thread computes 1 node x 4 cols
__global__ void k_gemm2(const float* __restrict__ W2) {
    __shared__ float Xs[64][65];
    __shared__ float Ws[64][16];
    int t = threadIdx.x;
    int n0 = blockIdx.x * 64;
    int r  = t >> 2;            // node within tile
    int c0 = (t & 3) << 2;      // col group

    // load x2 tile
#pragma unroll
    for (int it = 0; it < 16; ++it) {
        int fid = t + it * 256;
        int rr = fid >> 6;
        int k  = fid & 63;
        int gn = n0 + rr;
        Xs[rr][k] = (gn < NN) ? g_x2[(size_t)gn * HH + k] : 0.f;
    }
    // load W2 (64x16): exactly 256 float4s
    {
        int k = t >> 2;
        int c = (t & 3) << 2;
        *(float4*)&Ws[k][c] = *(const float4*)&W2[(size_t)k * CC + c];
    }
    __syncthreads();

    float acc0 = 0.f, acc1 = 0.f, acc2 = 0.f, acc3 = 0.f;
#pragma unroll
    for (int k = 0; k < 64; ++k) {
        float a = Xs[r][k];
        float4 b = *(const float4*)&Ws[k][c0];
        acc0 += a * b.x; acc1 += a * b.y; acc2 += a * b.z; acc3 += a * b.w;
    }
    int gn = n0 + r;
    if (gn < NN)
        *(float4*)&g_z[(size_t)gn * CC + c0] = make_float4(acc0, acc1, acc2, acc3);
}

// ---------------- agg2 + bias + log_softmax ---------------------------------
// one warp per node; all 32 lanes mirror dims c = lane & 15 (broadcast loads)
__global__ void k_agg2(const float* __restrict__ b2, float* __restrict__ out) {
    int gw = (blockIdx.x * blockDim.x + threadIdx.x) >> 5;
    if (gw >= NN) return;
    int lane = threadIdx.x & 31;
    int c = lane & 15;
    int n = gw;

    float di = g_dinv[n];
    float acc = g_z[(size_t)n * CC + c] * (di * di);

    int e0 = g_start[n], e1 = g_start[n + 1];
    for (int e = e0; e < e1; ++e) {
        int2  ce = g_csr[e];
        float w  = __int_as_float(ce.y);
        acc += w * g_z[(size_t)ce.x * CC + c];
    }
    acc += b2[c];

    // log_softmax over 16 dims within each half-warp (halves are identical)
    float m = acc;
#pragma unroll
    for (int o = 8; o >= 1; o >>= 1)
        m = fmaxf(m, __shfl_xor_sync(0xffffffffu, m, o, 16));
    float ex = expf(acc - m);
    float s = ex;
#pragma unroll
    for (int o = 8; o >= 1; o >>= 1)
        s += __shfl_xor_sync(0xffffffffu, s, o, 16);
    float res = acc - m - logf(s);

    if (lane < 16) out[(size_t)n * CC + c] = res;
}

// ---------------- launch -----------------------------------------------------
extern "C" void kernel_launch(void* const* d_in, const int* in_sizes, int n_in,
                              void* d_out, int out_size) {
    const float* x  = (const float*)d_in[0];
    const void*  ei = d_in[1];
    const float* W1 = (const float*)d_in[2];
    const float* b1 = (const float*)d_in[3];
    const float* W2 = (const float*)d_in[4];
    const float* b2 = (const float*)d_in[5];
    float* out = (float*)d_out;

    k_detect<<<1, 32>>>((const int*)ei);
    k_zero  <<<(NN + 255) / 256, 256>>>();
    k_hist  <<<(EE + 255) / 256, 256>>>(ei);
    k_dinv  <<<(NN + 255) / 256, 256>>>();
    k_scan1 <<<NB1, 1024>>>();
    k_scan2 <<<1, 128>>>();
    k_scan3 <<<NB1, 1024>>>();
    k_scatter<<<(EE + 255) / 256, 256>>>(ei);
    k_gemm1 <<<(NN + 63) / 64, 256>>>(x, W1);
    k_agg1  <<<12500, 256>>>(b1);
    k_gemm2 <<<(NN + 63) / 64, 256>>>(W2);
    k_agg2  <<<12500, 256>>>(b2, out);
}